// round 6
// baseline (speedup 1.0000x reference)
#include <cuda_runtime.h>
#include <cstdint>

// Problem shape (fixed for this dataset entry)
#define BB 8
#define CC 81
#define HH 96
#define WW 320
#define NN 16
#define HWSZ (HH * WW)            // 30720
#define TPB 256
#define BATCH 9                   // 81 = 9*9
#define NBLK (BB * HWSZ / (2 * TPB))   // 480 blocks, 2 px/thread

#define ALPHA_F   0.25f
#define FG_W_F    13.0f
#define BG_W_F    1.0f
#define DEPTH_MIN_F 0.001f
#define DEPTH_MAX_F 60.0f
#define NUM_BINS_I  80

// Cross-block accumulator (zero at load; last block resets -> deterministic per run)
__device__ float    g_scratch = 0.0f;
__device__ unsigned g_count   = 0u;

__global__ __launch_bounds__(TPB, 4) void ddn_loss_kernel(
    const float* __restrict__ logits,   // (B,C,H,W)
    const float* __restrict__ boxes,    // (B*N,4)
    const float* __restrict__ depths,   // (B*N,)
    float* __restrict__ out)            // scalar
{
    __shared__ int   sbu1[NN], sbv1[NN], sbu2[NN], sbv2[NN];
    __shared__ float sdep[NN];
    __shared__ float sred[8];

    const int t    = threadIdx.x;
    const int HW2  = HWSZ / 2;                   // 15360 (multiple of 256)
    const int g    = blockIdx.x * TPB + t;
    const int b    = g / HW2;                    // block never crosses batch
    const int rem2 = g - b * HW2;
    const int pix  = 2 * rem2;                   // even; pair never crosses a row
    const int h    = pix / WW;
    const int w0   = pix - h * WW;

    if (t < NN) {
        const int i = b * NN + t;
        sbu1[t] = (int)floorf(boxes[4 * i + 0]);
        sbv1[t] = (int)floorf(boxes[4 * i + 1]);
        sbu2[t] = (int)ceilf (boxes[4 * i + 2]);
        sbv2[t] = (int)ceilf (boxes[4 * i + 3]);
        sdep[t] = depths[i];
    }
    __syncthreads();

    // ---- Rasterize + LID binning for this thread's 2 pixels ----
    int   tgt[2];
    float wgt[2];
#pragma unroll
    for (int j = 0; j < 2; j++) {
        const int w = w0 + j;
        float dmin = 1e10f;
        bool  fg   = false;
#pragma unroll
        for (int i = 0; i < NN; i++) {
            const bool cov = (h >= sbv1[i]) & (h < sbv2[i]) &
                             (w >= sbu1[i]) & (w < sbu2[i]);
            if (cov) { fg = true; dmin = fminf(dmin, sdep[i]); }
        }
        const float d = fg ? dmin : 0.0f;
        const float bin_size = 2.0f * (DEPTH_MAX_F - DEPTH_MIN_F)
                               / ((float)NUM_BINS_I * (1.0f + (float)NUM_BINS_I));
        float idxf = -0.5f + 0.5f * sqrtf(1.0f + 8.0f * (d - DEPTH_MIN_F) / bin_size);
        if (!(idxf >= 0.0f) || idxf > (float)NUM_BINS_I) idxf = (float)NUM_BINS_I;
        tgt[j] = (int)idxf;
        wgt[j] = fg ? FG_W_F : BG_W_F;
    }

    // Base of this pixel pair within batch b's plane stack
    const float* __restrict__ gsrc = logits + (size_t)b * CC * HWSZ + pix;

    // Target logits fetched up front (lines also touched by the stream)
    const float xt0 = gsrc[(size_t)tgt[0] * HWSZ];
    const float xt1 = gsrc[(size_t)tgt[1] * HWSZ + 1];

    // ---- Stream 81 channels: 9-deep double-buffered float2 pipeline ----
    const float2* __restrict__ p2 = (const float2*)gsrc;
    const size_t stride2 = HWSZ / 2;

    float2 cur[BATCH], nxt[BATCH];
#pragma unroll
    for (int i = 0; i < BATCH; i++)
        cur[i] = p2[(size_t)i * stride2];

    float s0 = 0.f, s1 = 0.f;
#pragma unroll 1
    for (int blk = 0; blk < CC / BATCH - 1; blk++) {
        const float2* q = p2 + (size_t)(blk + 1) * BATCH * stride2;
#pragma unroll
        for (int i = 0; i < BATCH; i++)          // issue next batch (stays in flight)
            nxt[i] = q[(size_t)i * stride2];
#pragma unroll
        for (int i = 0; i < BATCH; i++) {        // consume current batch
            s0 += __expf(cur[i].x);
            s1 += __expf(cur[i].y);
        }
#pragma unroll
        for (int i = 0; i < BATCH; i++)
            cur[i] = nxt[i];
    }
#pragma unroll
    for (int i = 0; i < BATCH; i++) {
        s0 += __expf(cur[i].x);
        s1 += __expf(cur[i].y);
    }

    // ---- Focal loss per pixel, weighted ----
    float local;
    {
        float lp, pt;
        lp = xt0 - __logf(s0); pt = __expf(lp);
        local  = wgt[0] * (-ALPHA_F * (1.f - pt) * (1.f - pt) * lp);
        lp = xt1 - __logf(s1); pt = __expf(lp);
        local += wgt[1] * (-ALPHA_F * (1.f - pt) * (1.f - pt) * lp);
    }

    // ---- Block reduction ----
#pragma unroll
    for (int o = 16; o > 0; o >>= 1)
        local += __shfl_xor_sync(0xffffffffu, local, o);
    if ((t & 31) == 0) sred[t >> 5] = local;
    __syncthreads();

    // ---- Grid reduction without a separate memset node ----
    if (t == 0) {
        float v = 0.f;
#pragma unroll
        for (int i = 0; i < 8; i++) v += sred[i];
        atomicAdd(&g_scratch, v);
        __threadfence();
        const unsigned ticket = atomicAdd(&g_count, 1u);
        if (ticket == (unsigned)(gridDim.x - 1)) {
            // All prior scratch adds are visible (fence before ticket).
            const float tot = atomicAdd(&g_scratch, 0.0f);   // coherent read
            const float inv_np = 1.0f / (float)(BB * HH * WW);
            out[0] = tot * inv_np;
            // Reset for the next (graph-replayed) run: deterministic invariant.
            g_scratch = 0.0f;
            __threadfence();
            g_count = 0u;
        }
    }
}

extern "C" void kernel_launch(void* const* d_in, const int* in_sizes, int n_in,
                              void* d_out, int out_size) {
    const float* logits = (const float*)d_in[0];   // depth_logits (B,C,H,W) f32
    const float* boxes  = (const float*)d_in[1];   // gt_boxes2d (B*N,4) f32
    // d_in[2] = num_gt_per_img (scalar int, constant 16 for this shape)
    const float* depths = (const float*)d_in[3];   // gt_center_depth (B*N,) f32
    float* out = (float*)d_out;

    ddn_loss_kernel<<<NBLK, TPB>>>(logits, boxes, depths, out);
}

// round 7
// speedup vs baseline: 1.0961x; 1.0961x over previous
#include <cuda_runtime.h>
#include <cstdint>

// Problem shape (fixed for this dataset entry)
#define BB 8
#define CC 81
#define HH 96
#define WW 320
#define NN 16
#define HWSZ (HH * WW)            // 30720
#define TPB 256
#define BATCH 9                   // 81 = 9*9
#define NBLK (BB * HWSZ / TPB)    // 960 blocks, 1 px/thread

#define ALPHA_F   0.25f
#define FG_W_F    13.0f
#define BG_W_F    1.0f
#define DEPTH_MIN_F 0.001f
#define DEPTH_MAX_F 60.0f
#define NUM_BINS_I  80

// Cross-block accumulator (zero at load; last block resets -> deterministic per replay)
__device__ float    g_scratch = 0.0f;
__device__ unsigned g_count   = 0u;

__global__ __launch_bounds__(TPB, 6) void ddn_loss_kernel(
    const float* __restrict__ logits,   // (B,C,H,W)
    const float* __restrict__ boxes,    // (B*N,4)
    const float* __restrict__ depths,   // (B*N,)
    float* __restrict__ out)            // scalar
{
    __shared__ int   sbu1[NN], sbv1[NN], sbu2[NN], sbv2[NN];
    __shared__ float sdep[NN];
    __shared__ float sred[8];

    const int t   = threadIdx.x;
    const int g   = blockIdx.x * TPB + t;        // one pixel per thread
    const int b   = g / HWSZ;                    // block never crosses batch (30720 % 256 == 0)
    const int rem = g - b * HWSZ;
    const int h   = rem / WW;
    const int w   = rem - h * WW;

    if (t < NN) {
        const int i = b * NN + t;
        sbu1[t] = (int)floorf(boxes[4 * i + 0]);
        sbv1[t] = (int)floorf(boxes[4 * i + 1]);
        sbu2[t] = (int)ceilf (boxes[4 * i + 2]);
        sbv2[t] = (int)ceilf (boxes[4 * i + 3]);
        sdep[t] = depths[i];
    }
    __syncthreads();

    // ---- Rasterize + LID binning for this thread's pixel ----
    float dmin = 1e10f;
    bool  fg   = false;
#pragma unroll
    for (int i = 0; i < NN; i++) {
        const bool cov = (h >= sbv1[i]) & (h < sbv2[i]) &
                         (w >= sbu1[i]) & (w < sbu2[i]);
        if (cov) { fg = true; dmin = fminf(dmin, sdep[i]); }
    }
    const float d   = fg ? dmin : 0.0f;
    const float wgt = fg ? FG_W_F : BG_W_F;
    const float bin_size = 2.0f * (DEPTH_MAX_F - DEPTH_MIN_F)
                           / ((float)NUM_BINS_I * (1.0f + (float)NUM_BINS_I));
    float idxf = -0.5f + 0.5f * sqrtf(1.0f + 8.0f * (d - DEPTH_MIN_F) / bin_size);
    if (!(idxf >= 0.0f) || idxf > (float)NUM_BINS_I) idxf = (float)NUM_BINS_I;
    const int tgt = (int)idxf;                    // truncation toward zero

    // Base of this pixel within batch b's plane stack
    const float* __restrict__ gsrc = logits + (size_t)b * CC * HWSZ + rem;

    // Target logit fetched up front (line also touched by the stream; L2 hit)
    const float xt = gsrc[(size_t)tgt * HWSZ];

    // ---- Stream 81 channels: 9-deep double-buffered register pipeline ----
    float cur[BATCH], nxt[BATCH];
#pragma unroll
    for (int i = 0; i < BATCH; i++)
        cur[i] = gsrc[(size_t)i * HWSZ];

    float s = 0.f;
#pragma unroll 1
    for (int blk = 0; blk < CC / BATCH - 1; blk++) {
        const float* p = gsrc + (size_t)(blk + 1) * BATCH * HWSZ;
#pragma unroll
        for (int i = 0; i < BATCH; i++)          // issue next batch first (stays in flight)
            nxt[i] = p[(size_t)i * HWSZ];
#pragma unroll
        for (int i = 0; i < BATCH; i++)          // consume current batch
            s += __expf(cur[i]);
#pragma unroll
        for (int i = 0; i < BATCH; i++)
            cur[i] = nxt[i];
    }
#pragma unroll
    for (int i = 0; i < BATCH; i++)
        s += __expf(cur[i]);

    // ---- Focal loss, weighted ----
    const float lp = xt - __logf(s);
    const float pt = __expf(lp);
    float local = wgt * (-ALPHA_F * (1.f - pt) * (1.f - pt) * lp);

    // ---- Block reduction ----
#pragma unroll
    for (int o = 16; o > 0; o >>= 1)
        local += __shfl_xor_sync(0xffffffffu, local, o);
    if ((t & 31) == 0) sred[t >> 5] = local;
    __syncthreads();

    // ---- Grid reduction fused into the kernel (no separate memset node) ----
    if (t == 0) {
        float v = 0.f;
#pragma unroll
        for (int i = 0; i < 8; i++) v += sred[i];
        atomicAdd(&g_scratch, v);
        __threadfence();
        const unsigned ticket = atomicAdd(&g_count, 1u);
        if (ticket == (unsigned)(gridDim.x - 1)) {
            // All prior scratch adds are visible (fence before ticket).
            const float tot = atomicAdd(&g_scratch, 0.0f);   // coherent read
            const float inv_np = 1.0f / (float)(BB * HH * WW);
            out[0] = tot * inv_np;
            // Reset for the next graph replay: deterministic invariant.
            g_scratch = 0.0f;
            __threadfence();
            g_count = 0u;
        }
    }
}

extern "C" void kernel_launch(void* const* d_in, const int* in_sizes, int n_in,
                              void* d_out, int out_size) {
    const float* logits = (const float*)d_in[0];   // depth_logits (B,C,H,W) f32
    const float* boxes  = (const float*)d_in[1];   // gt_boxes2d (B*N,4) f32
    // d_in[2] = num_gt_per_img (scalar int, constant 16 for this shape)
    const float* depths = (const float*)d_in[3];   // gt_center_depth (B*N,) f32
    float* out = (float*)d_out;

    ddn_loss_kernel<<<NBLK, TPB>>>(logits, boxes, depths, out);
}